// round 4
// baseline (speedup 1.0000x reference)
#include <cuda_runtime.h>
#include <cstdint>

#define Bsz 64
#define Hd 128
#define Tt 12
#define Mm 50000
#define Kk 3
#define Ee 32
#define NDd 128
#define NCc 4
#define Nn 150000          // end token id; node one-hot width = Nn+1

#define RROWS 1024         // emb rows per distance block
#define DBLK 256           // distance kernel block size
#define CHUNKS ((Mm + RROWS - 1) / RROWS)   // 49 -> grid 3*49 = 147 ~= #SMs
#define RSTRIDE 36         // padded smem row stride (floats) for conflict-free LDS128

struct P {
    const float *z, *gt, *gn;
    const float *W1, *b1, *Wc, *bc, *Wh, *bh;
    const float *Wih, *bih, *Whh, *bhh;
    const float *Wt, *bt, *Wn, *bn, *Wdt, *bdt, *Wdn, *bdn, *emb;
    const int   *tids;
    float       *out;
};

// persistent per-launch state (rewritten every launch before any read)
__device__ float g_h[Bsz * Hd];
__device__ float g_c[Bsz * Hd];
__device__ __align__(16) float g_proj[Bsz * Ee];
__device__ float g_pp[Bsz];
__device__ float g_y[Bsz * NCc];
__device__ int g_tsel[Bsz];
__device__ unsigned long long g_best[Bsz];

__device__ __forceinline__ float sigm(float x) { return 1.0f / (1.0f + expf(-x)); }

// monotone map float -> uint32 preserving order (finite values)
__device__ __forceinline__ unsigned ford(float f) {
    unsigned u = __float_as_uint(f);
    unsigned mask = (u & 0x80000000u) ? 0xFFFFFFFFu : 0x80000000u;
    return u ^ mask;
}

// ---------------------------------------------------------------------------
// Per-step small kernel: finalize previous node pick, LSTM cell, type sample,
// projection for distance pass. One block per batch element b, 128 threads.
// ---------------------------------------------------------------------------
__global__ void __launch_bounds__(Hd) k_lstm(P p, int t) {
    int b = blockIdx.x;
    int i = threadIdx.x;

    __shared__ __align__(16) float xs[Hd];
    __shared__ __align__(16) float hs[Hd];
    __shared__ float hn[Hd];
    __shared__ float lg[NCc];
    __shared__ float ys[NCc];
    __shared__ int s_misc[2];   // [0]=node_id, [1]=t_idx

    float ci;
    if (t == 0) {
        // init: inter = tanh(z@W1^T + b1); h0 = tanh(inter@Wc^T+bc); c0 = tanh(inter@Wh^T+bh)
        __shared__ float inter[Hd];
        const float* zr = p.z + (size_t)b * NDd;
        const float* w1 = p.W1 + (size_t)i * NDd;
        float a = p.b1[i];
#pragma unroll 4
        for (int j = 0; j < NDd; j++) a += zr[j] * w1[j];
        inter[i] = tanhf(a);
        __syncthreads();
        const float* wc = p.Wc + (size_t)i * Hd;
        const float* wh = p.Wh + (size_t)i * Hd;
        float ah = p.bc[i], ac = p.bh[i];
#pragma unroll 4
        for (int j = 0; j < Hd; j++) { float v = inter[j]; ah += v * wc[j]; ac += v * wh[j]; }
        hs[i] = tanhf(ah);
        ci = tanhf(ac);
        xs[i] = 0.0f;
        __syncthreads();
    } else {
        // finalize step t-1: pick node from argmax result, emit one-hot, build x
        if (i < NCc) ys[i] = g_y[b * NCc + i];
        if (i == 0) {
            int tprev = g_tsel[b];
            int node;
            if (tprev >= Kk) {
                node = Nn;
            } else {
                unsigned mm = ~(unsigned)(g_best[b] & 0xFFFFFFFFull);
                node = p.tids[tprev * Mm + (int)mm];
            }
            s_misc[0] = node;
            p.out[(size_t)Bsz * Tt * NCc +
                  ((size_t)b * Tt + (t - 1)) * (size_t)(Nn + 1) + node] = 1.0f;
        }
        __syncthreads();
        int node = s_misc[0];
        float xv = p.bdt[i] + p.bdn[i] + p.Wdn[(size_t)i * (Nn + 1) + node];
#pragma unroll
        for (int j = 0; j < NCc; j++) xv += ys[j] * p.Wdt[i * NCc + j];
        xs[i] = xv;
        hs[i] = g_h[b * Hd + i];
        ci = g_c[b * Hd + i];
        __syncthreads();
    }

    // LSTM gates: thread i computes gate rows i, i+H, i+2H, i+3H (i,f,g,o)
    float gi = p.bih[i]          + p.bhh[i];
    float gf = p.bih[i + Hd]     + p.bhh[i + Hd];
    float gg = p.bih[i + 2 * Hd] + p.bhh[i + 2 * Hd];
    float go = p.bih[i + 3 * Hd] + p.bhh[i + 3 * Hd];
    {
        const float4* xi = (const float4*)xs;
        const float4* hi = (const float4*)hs;
        const float4* wi0 = (const float4*)(p.Wih + (size_t)i * Hd);
        const float4* wi1 = (const float4*)(p.Wih + (size_t)(i + Hd) * Hd);
        const float4* wi2 = (const float4*)(p.Wih + (size_t)(i + 2 * Hd) * Hd);
        const float4* wi3 = (const float4*)(p.Wih + (size_t)(i + 3 * Hd) * Hd);
        const float4* wh0 = (const float4*)(p.Whh + (size_t)i * Hd);
        const float4* wh1 = (const float4*)(p.Whh + (size_t)(i + Hd) * Hd);
        const float4* wh2 = (const float4*)(p.Whh + (size_t)(i + 2 * Hd) * Hd);
        const float4* wh3 = (const float4*)(p.Whh + (size_t)(i + 3 * Hd) * Hd);
#pragma unroll 8
        for (int j = 0; j < Hd / 4; j++) {
            float4 xv = xi[j], hv = hi[j], a;
            a = wi0[j]; gi += xv.x * a.x + xv.y * a.y + xv.z * a.z + xv.w * a.w;
            a = wh0[j]; gi += hv.x * a.x + hv.y * a.y + hv.z * a.z + hv.w * a.w;
            a = wi1[j]; gf += xv.x * a.x + xv.y * a.y + xv.z * a.z + xv.w * a.w;
            a = wh1[j]; gf += hv.x * a.x + hv.y * a.y + hv.z * a.z + hv.w * a.w;
            a = wi2[j]; gg += xv.x * a.x + xv.y * a.y + xv.z * a.z + xv.w * a.w;
            a = wh2[j]; gg += hv.x * a.x + hv.y * a.y + hv.z * a.z + hv.w * a.w;
            a = wi3[j]; go += xv.x * a.x + xv.y * a.y + xv.z * a.z + xv.w * a.w;
            a = wh3[j]; go += hv.x * a.x + hv.y * a.y + hv.z * a.z + hv.w * a.w;
        }
    }
    float cn = sigm(gf) * ci + sigm(gi) * tanhf(gg);
    float hv = sigm(go) * tanhf(cn);
    g_c[b * Hd + i] = cn;
    g_h[b * Hd + i] = hv;
    hn[i] = hv;
    __syncthreads();

    // type logits: warp w computes logit w (NC=4)
    int w = i >> 5, l = i & 31;
    if (w < NCc) {
        const float* wt = p.Wt + w * Hd;
        float a = 0.0f;
#pragma unroll
        for (int j = l; j < Hd; j += 32) a += hn[j] * wt[j];
#pragma unroll
        for (int o = 16; o; o >>= 1) a += __shfl_down_sync(0xffffffffu, a, o);
        if (l == 0)
            lg[w] = (a + p.bt[w] + p.gt[((size_t)t * Bsz + b) * NCc + w]) / 3.0f;
    }
    __syncthreads();

    if (i == 0) {
        float v0 = lg[0], v1 = lg[1], v2 = lg[2], v3 = lg[3];
        float mx = fmaxf(fmaxf(v0, v1), fmaxf(v2, v3));
        float e0 = expf(v0 - mx), e1 = expf(v1 - mx), e2 = expf(v2 - mx), e3 = expf(v3 - mx);
        float inv = 1.0f / (e0 + e1 + e2 + e3);
        float yss[4] = { e0 * inv, e1 * inv, e2 * inv, e3 * inv };
        int am = 0; float bv = yss[0];
        if (yss[1] > bv) { bv = yss[1]; am = 1; }
        if (yss[2] > bv) { bv = yss[2]; am = 2; }
        if (yss[3] > bv) { bv = yss[3]; am = 3; }
        float yv[4] = { 0.f, 0.f, 0.f, 0.f };
        yv[am] = (1.0f - yss[am]) + yss[am];   // straight-through hard value (bit-faithful)
#pragma unroll
        for (int j = 0; j < NCc; j++) {
            g_y[b * NCc + j] = yv[j];
            p.out[((size_t)b * Tt + t) * NCc + j] = yv[j];
        }
        g_tsel[b] = am;
        g_best[b] = 0ull;       // reset argmax accumulator for this step
        s_misc[1] = am;
    }
    __syncthreads();

    // projection for distance pass (skip when type == end)
    int am = s_misc[1];
    if (am < Kk && i < Ee) {
        const float* wn = p.Wn + ((size_t)am * Ee + i) * Hd;
        float a = p.bn[am * Ee + i];
#pragma unroll 4
        for (int j = 0; j < Hd; j++) a += hn[j] * wn[j];
        g_proj[b * Ee + i] = a;
        float s2 = a * a;
#pragma unroll
        for (int o = 16; o; o >>= 1) s2 += __shfl_down_sync(0xffffffffu, s2, o);
        if (i == 0) g_pp[b] = s2;
    }
}

// ---------------------------------------------------------------------------
// Distance + gumbel-max argmax over M nodes. Block = (k, m-chunk of RROWS).
// emb tile staged in smem once, reused for every active batch element of that
// type (8 b's per pass, 4x8 register tile per thread). Per-b running best is
// block-reduced and atomicMax'd into g_best[b] as packed (score_bits, ~m).
// ---------------------------------------------------------------------------
__global__ void __launch_bounds__(DBLK) k_dist(P p, int t) {
    extern __shared__ float sm[];
    float* embs  = sm;                               // RROWS * RSTRIDE
    float* esqs  = embs + RROWS * RSTRIDE;           // RROWS
    float* projS = esqs + RROWS;                     // 8 * Ee
    unsigned long long* reds = (unsigned long long*)(projS + 8 * Ee);  // 64

    __shared__ int blist[Bsz];
    __shared__ int s_gc;

    int k = blockIdx.x / CHUNKS;
    int chunk = blockIdx.x - k * CHUNKS;
    int m0 = chunk * RROWS;
    int rows = min(RROWS, Mm - m0);
    int tid = threadIdx.x;

    if (tid == 0) {
        int c = 0;
        for (int b = 0; b < Bsz; b++)
            if (g_tsel[b] == k) blist[c++] = b;
        s_gc = c;
    }

    // stage emb tile (zero-pad tail rows), conflict-free padded layout
    const float4* ebase = (const float4*)(p.emb + ((size_t)k * Mm + m0) * Ee);
    int vrf4 = rows * 8;
    for (int idx = tid; idx < RROWS * 8; idx += DBLK) {
        float4 v = (idx < vrf4) ? __ldg(ebase + idx) : make_float4(0.f, 0.f, 0.f, 0.f);
        int r = idx >> 3, q = idx & 7;
        *(float4*)(embs + r * RSTRIDE + 4 * q) = v;
    }
    __syncthreads();

    // per-row squared norms (pad rows get +huge so they never win)
    for (int r = tid; r < RROWS; r += DBLK) {
        float s = 0.0f;
#pragma unroll
        for (int q = 0; q < 8; q++) {
            float4 v = *(float4*)(embs + r * RSTRIDE + 4 * q);
            s += v.x * v.x + v.y * v.y + v.z * v.z + v.w * v.w;
        }
        esqs[r] = (r < rows) ? s : 1e30f;
    }
    int gc = s_gc;
    __syncthreads();
    if (gc == 0) return;

    const float* gnt = p.gn + (size_t)t * Bsz * Mm;
    int warp = tid >> 5, lane = tid & 31;

    for (int p0 = 0; p0 < gc; p0 += 8) {
        int nb = min(8, gc - p0);

        // stage up to 8 projection vectors
        {
            int j = tid >> 5;       // 256 threads = 8 x 32
            int e = tid & 31;
            float v = 0.0f;
            if (j < nb) v = g_proj[blist[p0 + j] * Ee + e];
            projS[j * Ee + e] = v;
        }
        __syncthreads();

        int bj[8]; float ppj[8];
#pragma unroll
        for (int j = 0; j < 8; j++) {
            int bb = blist[p0 + (j < nb ? j : 0)];
            bj[j] = bb;
            ppj[j] = g_pp[bb];
        }

        float acc[4][8];
#pragma unroll
        for (int i4 = 0; i4 < 4; i4++)
#pragma unroll
            for (int j = 0; j < 8; j++) acc[i4][j] = 0.0f;

#pragma unroll
        for (int q = 0; q < 8; q++) {
            float4 av[4];
#pragma unroll
            for (int i4 = 0; i4 < 4; i4++)
                av[i4] = *(float4*)(embs + (size_t)(i4 * DBLK + tid) * RSTRIDE + 4 * q);
#pragma unroll
            for (int j = 0; j < 8; j++) {
                float4 bv = *(float4*)(projS + j * Ee + 4 * q);
#pragma unroll
                for (int i4 = 0; i4 < 4; i4++)
                    acc[i4][j] += av[i4].x * bv.x + av[i4].y * bv.y +
                                  av[i4].z * bv.z + av[i4].w * bv.w;
            }
        }

        unsigned long long bestk[8];
#pragma unroll
        for (int j = 0; j < 8; j++) bestk[j] = 0ull;

#pragma unroll
        for (int i4 = 0; i4 < 4; i4++) {
            int ml = i4 * DBLK + tid;
            bool valid = (ml < rows);
            float esq = esqs[ml];
            int mg = m0 + ml;
#pragma unroll
            for (int j = 0; j < 8; j++) {
                if (j < nb && valid) {
                    float d2 = esq - 2.0f * acc[i4][j] + ppj[j];
                    float dist = sqrtf(fmaxf(d2, 0.0f));
                    float sc = __ldg(gnt + (size_t)bj[j] * Mm + mg) - dist;
                    unsigned long long key =
                        ((unsigned long long)ford(sc) << 32) | (unsigned)(~(unsigned)mg);
                    if (key > bestk[j]) bestk[j] = key;
                }
            }
        }

        // block argmax reduction per b, then one atomic per (block, b)
#pragma unroll
        for (int j = 0; j < 8; j++) {
            unsigned long long kk = bestk[j];
#pragma unroll
            for (int o = 16; o; o >>= 1) {
                unsigned long long ot = __shfl_down_sync(0xffffffffu, kk, o);
                if (ot > kk) kk = ot;
            }
            if (lane == 0) reds[warp * 8 + j] = kk;
        }
        __syncthreads();
        if (tid < 8 && tid < nb) {
            int j = tid;
            unsigned long long kk = reds[j];
#pragma unroll
            for (int w2 = 1; w2 < 8; w2++) {
                unsigned long long ot = reds[w2 * 8 + j];
                if (ot > kk) kk = ot;
            }
            atomicMax(&g_best[bj[j]], kk);
        }
        __syncthreads();
    }
}

// finalize last step's node pick (one-hot only; no further x needed)
__global__ void k_final(P p) {
    int b = threadIdx.x;
    if (b >= Bsz) return;
    int tl = g_tsel[b];
    int node;
    if (tl >= Kk) {
        node = Nn;
    } else {
        unsigned mm = ~(unsigned)(g_best[b] & 0xFFFFFFFFull);
        node = p.tids[tl * Mm + (int)mm];
    }
    p.out[(size_t)Bsz * Tt * NCc +
          ((size_t)b * Tt + (Tt - 1)) * (size_t)(Nn + 1) + node] = 1.0f;
}

extern "C" void kernel_launch(void* const* d_in, const int* in_sizes, int n_in,
                              void* d_out, int out_size) {
    (void)in_sizes; (void)n_in;
    P p;
    p.z    = (const float*)d_in[0];
    p.gt   = (const float*)d_in[1];
    p.gn   = (const float*)d_in[2];
    p.W1   = (const float*)d_in[3];
    p.b1   = (const float*)d_in[4];
    p.Wc   = (const float*)d_in[5];
    p.bc   = (const float*)d_in[6];
    p.Wh   = (const float*)d_in[7];
    p.bh   = (const float*)d_in[8];
    p.Wih  = (const float*)d_in[9];
    p.bih  = (const float*)d_in[10];
    p.Whh  = (const float*)d_in[11];
    p.bhh  = (const float*)d_in[12];
    p.Wt   = (const float*)d_in[13];
    p.bt   = (const float*)d_in[14];
    p.Wn   = (const float*)d_in[15];
    p.bn   = (const float*)d_in[16];
    p.Wdt  = (const float*)d_in[17];
    p.bdt  = (const float*)d_in[18];
    p.Wdn  = (const float*)d_in[19];
    p.bdn  = (const float*)d_in[20];
    p.emb  = (const float*)d_in[21];
    p.tids = (const int*)d_in[22];
    p.out  = (float*)d_out;

    const int DSMEM = (RROWS * RSTRIDE + RROWS + 8 * Ee) * 4 + 64 * 8;  // 153088 B
    static int smem_ok = -1;
    if (smem_ok < 0) {
        cudaError_t e = cudaFuncSetAttribute(
            k_dist, cudaFuncAttributeMaxDynamicSharedMemorySize, DSMEM);
        smem_ok = (e == cudaSuccess) ? 1 : 0;
    }

    // zero the whole output (type region is fully overwritten later)
    cudaMemsetAsync(d_out, 0, (size_t)out_size * sizeof(float));

    for (int t = 0; t < Tt; t++) {
        k_lstm<<<Bsz, Hd>>>(p, t);
        k_dist<<<Kk * CHUNKS, DBLK, DSMEM>>>(p, t);
    }
    k_final<<<1, Bsz>>>(p);
}

// round 7
// speedup vs baseline: 1.8758x; 1.8758x over previous
#include <cuda_runtime.h>
#include <cstdint>

#define Bsz 64
#define Hd 128
#define Tt 12
#define Mm 50000
#define Kk 3
#define Ee 32
#define NDd 128
#define NCc 4
#define Nn 150000          // end token id; node one-hot width = Nn+1

#define RROWS 512          // emb rows per distance block (77 KB smem -> 2 blocks/SM)
#define DBLK 256           // block size
#define RPT (RROWS / DBLK) // rows per thread = 2
#define CHUNKS ((Mm + RROWS - 1) / RROWS)   // 98
#define NBLK (Kk * CHUNKS)                  // 294 blocks = one wave at occ 2
#define RSTRIDE 36         // padded smem row stride (floats), conflict-free LDS128

struct P {
    const float *z, *gt, *gn;
    const float *W1, *b1, *Wc, *bc, *Wh, *bh;
    const float *Wih, *bih, *Whh, *bhh;
    const float *Wt, *bt, *Wn, *bn, *Wdt, *bdt, *Wdn, *bdn, *emb;
    const int   *tids;
    float       *out;
};

// persistent per-launch state (rewritten every launch before any read)
__device__ float g_h[Bsz * Hd];
__device__ float g_c[Bsz * Hd];
__device__ __align__(16) float g_proj[Bsz * Ee];
__device__ float g_pp[Bsz];
__device__ float g_y[Bsz * NCc];
__device__ int g_tsel[Bsz];
__device__ unsigned long long g_best[Bsz];

__device__ __forceinline__ float sigm(float x) { return 1.0f / (1.0f + expf(-x)); }

// monotone map float -> uint32 preserving order (finite values)
__device__ __forceinline__ unsigned ford(float f) {
    unsigned u = __float_as_uint(f);
    unsigned mask = (u & 0x80000000u) ? 0xFFFFFFFFu : 0x80000000u;
    return u ^ mask;
}

// ---------------------------------------------------------------------------
// Per-step kernel: finalize previous node pick, LSTM cell, type sample,
// projection. One block per batch element b, 256 threads (2-way gate split).
// ---------------------------------------------------------------------------
__global__ void __launch_bounds__(2 * Hd) k_lstm(P p, int t) {
    const int b = blockIdx.x;
    const int tid = threadIdx.x;
    const int i = tid & (Hd - 1);
    const int grp = tid >> 7;          // 0 or 1
    const int warp = tid >> 5, lane = tid & 31;

    __shared__ __align__(16) float xs[Hd];
    __shared__ __align__(16) float s_h[Hd];
    __shared__ float s_c[Hd];
    __shared__ float gsm[2 * Hd];      // also scratch for inter at t==0
    __shared__ float projv[Ee];
    __shared__ float lg[NCc];
    __shared__ float ys[NCc];
    __shared__ int s_misc[2];          // [0]=node_id, [1]=t_idx

    if (t == 0) {
        // inter = tanh(z@W1^T + b1)
        if (tid < Hd) {
            const float* zr = p.z + (size_t)b * NDd;
            const float* w1 = p.W1 + (size_t)tid * NDd;
            float a = p.b1[tid];
#pragma unroll 4
        for (int j = 0; j < NDd; j++) a += zr[j] * w1[j];
            gsm[tid] = tanhf(a);
        }
        __syncthreads();
        // h0 = tanh(inter@Wc^T+bc) (grp0); c0 = tanh(inter@Wh^T+bh) (grp1)
        {
            const float* W  = (grp == 0) ? p.Wc : p.Wh;
            const float* bb = (grp == 0) ? p.bc : p.bh;
            float a = bb[i];
#pragma unroll 4
            for (int j = 0; j < Hd; j++) a += gsm[j] * W[(size_t)i * Hd + j];
            if (grp == 0) { s_h[i] = tanhf(a); xs[i] = 0.0f; }
            else          { s_c[i] = tanhf(a); }
        }
        __syncthreads();
    } else {
        // finalize step t-1: pick node, emit one-hot, build x
        if (tid < NCc) ys[tid] = g_y[b * NCc + tid];
        if (tid == 0) {
            int tprev = g_tsel[b];
            int node;
            if (tprev >= Kk) node = Nn;
            else {
                unsigned mm = ~(unsigned)(g_best[b] & 0xFFFFFFFFull);
                node = p.tids[tprev * Mm + (int)mm];
            }
            s_misc[0] = node;
            p.out[(size_t)Bsz * Tt * NCc +
                  ((size_t)b * Tt + (t - 1)) * (size_t)(Nn + 1) + node] = 1.0f;
        }
        __syncthreads();
        if (grp == 0) {
            int node = s_misc[0];
            float xv = p.bdt[i] + p.bdn[i] + p.Wdn[(size_t)i * (Nn + 1) + node];
#pragma unroll
            for (int j = 0; j < NCc; j++) xv += ys[j] * p.Wdt[i * NCc + j];
            xs[i] = xv;
            s_h[i] = g_h[b * Hd + i];
        } else {
            s_c[i] = g_c[b * Hd + i];
        }
        __syncthreads();
    }

    // gates 2-way split: grp0 -> rows i (gate i), i+2H (gate g)
    //                    grp1 -> rows i+H (gate f), i+3H (gate o)
    const int r0 = i + grp * Hd;
    const int r1 = i + (2 + grp) * Hd;
    float a0 = p.bih[r0] + p.bhh[r0];
    float a1 = p.bih[r1] + p.bhh[r1];
    {
        const float4* xi  = (const float4*)xs;
        const float4* hi  = (const float4*)s_h;
        const float4* wi0 = (const float4*)(p.Wih + (size_t)r0 * Hd);
        const float4* wi1 = (const float4*)(p.Wih + (size_t)r1 * Hd);
        const float4* wh0 = (const float4*)(p.Whh + (size_t)r0 * Hd);
        const float4* wh1 = (const float4*)(p.Whh + (size_t)r1 * Hd);
#pragma unroll 8
        for (int j = 0; j < Hd / 4; j++) {
            float4 xv = xi[j], hv = hi[j], a;
            a = wi0[j]; a0 += xv.x * a.x + xv.y * a.y + xv.z * a.z + xv.w * a.w;
            a = wh0[j]; a0 += hv.x * a.x + hv.y * a.y + hv.z * a.z + hv.w * a.w;
            a = wi1[j]; a1 += xv.x * a.x + xv.y * a.y + xv.z * a.z + xv.w * a.w;
            a = wh1[j]; a1 += hv.x * a.x + hv.y * a.y + hv.z * a.z + hv.w * a.w;
        }
    }
    if (grp == 1) { gsm[i] = a0; gsm[Hd + i] = a1; }   // stash f, o
    __syncthreads();
    if (grp == 0) {
        float cn = sigm(gsm[i]) * s_c[i] + sigm(a0) * tanhf(a1);
        float hv = sigm(gsm[Hd + i]) * tanhf(cn);
        g_c[b * Hd + i] = cn;
        g_h[b * Hd + i] = hv;
        s_h[i] = hv;
    }
    __syncthreads();

    // type logits: warps 0..3, one logit each
    if (warp < NCc) {
        const float* wt = p.Wt + warp * Hd;
        float a = 0.0f;
#pragma unroll
        for (int j = lane; j < Hd; j += 32) a += s_h[j] * wt[j];
#pragma unroll
        for (int o = 16; o; o >>= 1) a += __shfl_down_sync(0xffffffffu, a, o);
        if (lane == 0)
            lg[warp] = (a + p.bt[warp] + p.gt[((size_t)t * Bsz + b) * NCc + warp]) / 3.0f;
    }
    __syncthreads();

    if (tid == 0) {
        float v0 = lg[0], v1 = lg[1], v2 = lg[2], v3 = lg[3];
        float mx = fmaxf(fmaxf(v0, v1), fmaxf(v2, v3));
        float e0 = expf(v0 - mx), e1 = expf(v1 - mx), e2 = expf(v2 - mx), e3 = expf(v3 - mx);
        float inv = 1.0f / (e0 + e1 + e2 + e3);
        float yss[4] = { e0 * inv, e1 * inv, e2 * inv, e3 * inv };
        int am = 0; float bv = yss[0];
        if (yss[1] > bv) { bv = yss[1]; am = 1; }
        if (yss[2] > bv) { bv = yss[2]; am = 2; }
        if (yss[3] > bv) { bv = yss[3]; am = 3; }
        float yv[4] = { 0.f, 0.f, 0.f, 0.f };
        yv[am] = (1.0f - yss[am]) + yss[am];   // straight-through hard value
#pragma unroll
        for (int j = 0; j < NCc; j++) {
            g_y[b * NCc + j] = yv[j];
            p.out[((size_t)b * Tt + t) * NCc + j] = yv[j];
        }
        g_tsel[b] = am;
        g_best[b] = 0ull;       // reset argmax accumulator for this step
        s_misc[1] = am;
    }
    __syncthreads();

    // projection proj = h @ Wn[am]^T + bn[am] (skip when type == end);
    // 8 threads per output element
    int am = s_misc[1];
    if (am < Kk) {
        int e = tid >> 3, part = tid & 7;
        const float* wn = p.Wn + ((size_t)am * Ee + e) * Hd;
        float a = 0.0f;
#pragma unroll
        for (int jj = 0; jj < 16; jj++) { int j = part + 8 * jj; a += s_h[j] * wn[j]; }
        a += __shfl_down_sync(0xffffffffu, a, 4, 8);
        a += __shfl_down_sync(0xffffffffu, a, 2, 8);
        a += __shfl_down_sync(0xffffffffu, a, 1, 8);
        if (part == 0) {
            a += p.bn[am * Ee + e];
            g_proj[b * Ee + e] = a;
            projv[e] = a;
        }
        __syncthreads();
        if (tid < 32) {
            float v = projv[tid];
            float s2 = v * v;
#pragma unroll
            for (int o = 16; o; o >>= 1) s2 += __shfl_down_sync(0xffffffffu, s2, o);
            if (tid == 0) g_pp[b] = s2;
        }
    }
}

// ---------------------------------------------------------------------------
// Distance + gumbel-max argmax. Block = (k, 512-row emb chunk), 2 blocks/SM.
// emb tile staged in smem (hits L2 after step 0), reused across 8-b passes;
// gn prefetched into registers BEFORE the FMA loop (MLP ~16).
// ---------------------------------------------------------------------------
__global__ void __launch_bounds__(DBLK, 2) k_dist(P p, int t) {
    extern __shared__ float sm[];
    float* embs  = sm;                               // RROWS * RSTRIDE
    float* esqs  = embs + RROWS * RSTRIDE;           // RROWS
    float* projS = esqs + RROWS;                     // 8 * Ee
    unsigned long long* reds = (unsigned long long*)(projS + 8 * Ee);  // 64

    __shared__ int blist[Bsz];
    __shared__ int s_gc;

    const int k = blockIdx.x / CHUNKS;
    const int chunk = blockIdx.x - k * CHUNKS;
    const int m0 = chunk * RROWS;
    const int rows = min(RROWS, Mm - m0);
    const int tid = threadIdx.x;
    const int warp = tid >> 5, lane = tid & 31;

    if (tid == 0) {
        int c = 0;
        for (int b = 0; b < Bsz; b++)
            if (g_tsel[b] == k) blist[c++] = b;
        s_gc = c;
    }

    // stage emb tile (zero-pad tail rows), conflict-free padded layout
    {
        const float4* ebase = (const float4*)(p.emb + ((size_t)k * Mm + m0) * Ee);
        int vrf4 = rows * 8;
        for (int idx = tid; idx < RROWS * 8; idx += DBLK) {
            float4 v = (idx < vrf4) ? __ldg(ebase + idx) : make_float4(0.f, 0.f, 0.f, 0.f);
            int r = idx >> 3, q = idx & 7;
            *(float4*)(embs + r * RSTRIDE + 4 * q) = v;
        }
    }
    __syncthreads();

    // per-row squared norms (pad rows never win)
    for (int r = tid; r < RROWS; r += DBLK) {
        float s = 0.0f;
#pragma unroll
        for (int q = 0; q < 8; q++) {
            float4 v = *(float4*)(embs + r * RSTRIDE + 4 * q);
            s += v.x * v.x + v.y * v.y + v.z * v.z + v.w * v.w;
        }
        esqs[r] = (r < rows) ? s : 1e30f;
    }
    int gc = s_gc;
    __syncthreads();
    if (gc == 0) return;

    const float* gnt = p.gn + (size_t)t * Bsz * Mm;

    for (int p0 = 0; p0 < gc; p0 += 8) {
        int nb = min(8, gc - p0);

        // stage up to 8 projection vectors into smem
        {
            int j = tid >> 5;           // 8 x 32
            int e = tid & 31;
            float v = 0.0f;
            if (j < nb) v = g_proj[blist[p0 + j] * Ee + e];
            projS[j * Ee + e] = v;
        }

        int bj[8]; float ppj[8];
#pragma unroll
        for (int j = 0; j < 8; j++) {
            int bb = blist[p0 + (j < nb ? j : 0)];
            bj[j] = bb;
            ppj[j] = g_pp[bb];
        }

        // prefetch gumbel noise: 16 independent DRAM loads in flight per thread
        float gnv[RPT][8];
#pragma unroll
        for (int i2 = 0; i2 < RPT; i2++) {
            int ml = i2 * DBLK + tid;
            int mg = m0 + ml;
            bool valid = (ml < rows);
#pragma unroll
            for (int j = 0; j < 8; j++)
                gnv[i2][j] = (j < nb && valid)
                             ? __ldg(gnt + (size_t)bj[j] * Mm + mg) : 0.0f;
        }
        __syncthreads();    // projS ready

        float acc[RPT][8];
#pragma unroll
        for (int i2 = 0; i2 < RPT; i2++)
#pragma unroll
            for (int j = 0; j < 8; j++) acc[i2][j] = 0.0f;

#pragma unroll
        for (int q = 0; q < 8; q++) {
            float4 av[RPT];
#pragma unroll
            for (int i2 = 0; i2 < RPT; i2++)
                av[i2] = *(float4*)(embs + (size_t)(i2 * DBLK + tid) * RSTRIDE + 4 * q);
#pragma unroll
            for (int j = 0; j < 8; j++) {
                float4 bv = *(float4*)(projS + j * Ee + 4 * q);
#pragma unroll
                for (int i2 = 0; i2 < RPT; i2++)
                    acc[i2][j] += av[i2].x * bv.x + av[i2].y * bv.y +
                                  av[i2].z * bv.z + av[i2].w * bv.w;
            }
        }

        unsigned long long bestk[8];
#pragma unroll
        for (int j = 0; j < 8; j++) bestk[j] = 0ull;

#pragma unroll
        for (int i2 = 0; i2 < RPT; i2++) {
            int ml = i2 * DBLK + tid;
            bool valid = (ml < rows);
            float esq = esqs[ml];
            int mg = m0 + ml;
#pragma unroll
            for (int j = 0; j < 8; j++) {
                if (j < nb && valid) {
                    float d2 = esq - 2.0f * acc[i2][j] + ppj[j];
                    float dist = sqrtf(fmaxf(d2, 0.0f));
                    float sc = gnv[i2][j] - dist;
                    unsigned long long key =
                        ((unsigned long long)ford(sc) << 32) | (unsigned)(~(unsigned)mg);
                    if (key > bestk[j]) bestk[j] = key;
                }
            }
        }

        // block reduction per b, one atomicMax per (block, b)
#pragma unroll
        for (int j = 0; j < 8; j++) {
            unsigned long long kk = bestk[j];
#pragma unroll
            for (int o = 16; o; o >>= 1) {
                unsigned long long ot = __shfl_down_sync(0xffffffffu, kk, o);
                if (ot > kk) kk = ot;
            }
            if (lane == 0) reds[warp * 8 + j] = kk;
        }
        __syncthreads();
        if (tid < 8 && tid < nb) {
            int j = tid;
            unsigned long long kk = reds[j];
#pragma unroll
            for (int w2 = 1; w2 < 8; w2++) {
                unsigned long long ot = reds[w2 * 8 + j];
                if (ot > kk) kk = ot;
            }
            atomicMax(&g_best[bj[j]], kk);
        }
        __syncthreads();
    }
}

// finalize last step's node pick (one-hot only)
__global__ void k_final(P p) {
    int b = threadIdx.x;
    if (b >= Bsz) return;
    int tl = g_tsel[b];
    int node;
    if (tl >= Kk) node = Nn;
    else {
        unsigned mm = ~(unsigned)(g_best[b] & 0xFFFFFFFFull);
        node = p.tids[tl * Mm + (int)mm];
    }
    p.out[(size_t)Bsz * Tt * NCc +
          ((size_t)b * Tt + (Tt - 1)) * (size_t)(Nn + 1) + node] = 1.0f;
}

extern "C" void kernel_launch(void* const* d_in, const int* in_sizes, int n_in,
                              void* d_out, int out_size) {
    (void)in_sizes; (void)n_in;
    P p;
    p.z    = (const float*)d_in[0];
    p.gt   = (const float*)d_in[1];
    p.gn   = (const float*)d_in[2];
    p.W1   = (const float*)d_in[3];
    p.b1   = (const float*)d_in[4];
    p.Wc   = (const float*)d_in[5];
    p.bc   = (const float*)d_in[6];
    p.Wh   = (const float*)d_in[7];
    p.bh   = (const float*)d_in[8];
    p.Wih  = (const float*)d_in[9];
    p.bih  = (const float*)d_in[10];
    p.Whh  = (const float*)d_in[11];
    p.bhh  = (const float*)d_in[12];
    p.Wt   = (const float*)d_in[13];
    p.bt   = (const float*)d_in[14];
    p.Wn   = (const float*)d_in[15];
    p.bn   = (const float*)d_in[16];
    p.Wdt  = (const float*)d_in[17];
    p.bdt  = (const float*)d_in[18];
    p.Wdn  = (const float*)d_in[19];
    p.bdn  = (const float*)d_in[20];
    p.emb  = (const float*)d_in[21];
    p.tids = (const int*)d_in[22];
    p.out  = (float*)d_out;

    const int DSMEM = (RROWS * RSTRIDE + RROWS + 8 * Ee) * 4 + 64 * 8;  // 77312 B
    cudaFuncSetAttribute(k_dist, cudaFuncAttributeMaxDynamicSharedMemorySize, DSMEM);

    // zero the whole output (type region is fully overwritten later)
    cudaMemsetAsync(d_out, 0, (size_t)out_size * sizeof(float));

    for (int t = 0; t < Tt; t++) {
        k_lstm<<<Bsz, 2 * Hd>>>(p, t);
        k_dist<<<NBLK, DBLK, DSMEM>>>(p, t);
    }
    k_final<<<1, Bsz>>>(p);
}